// round 3
// baseline (speedup 1.0000x reference)
#include <cuda_runtime.h>
#include <cuda_bf16.h>
#include <cstdint>

// GCNLayer_EdgeCat on GB300 — tensor-core (bf16 3-split) version.
//   Weight-split algebra: We=[We1;We2;We3], Wn=[Wn1;Wn2]:
//     A  = nf@We1+be, C = nf@We3, An = nf@Wn1+bn   (node precompute)
//     m  = ReLU(A[src] + ef@We2 + C[dst])           (edge kernel)
//     out1 = ReLU(An + mean@Wn2) + nf               (node update)
//     out2 = m + ef
//   All [*,128]@[128,128] GEMMs run as mma.sync.m16n8k16.bf16 with the
//   fp32 operand split x = hi(bf16) + lo(bf16); A@B ~= AhBh + AhBl + AlBh.

#define H        128
#define H4       32
#define NNODE    50000
#define NEDGE    800000
#define BT       128          // rows per block tile
#define NT       256          // threads per block (8 warps x 16 rows)
#define STRIDE   136          // bf16 row stride (padded: conflict-free LDSM)
#define TILE     (BT * STRIDE)

__device__ float g_A  [(size_t)NNODE * H];
__device__ float g_C  [(size_t)NNODE * H];
__device__ float g_An [(size_t)NNODE * H];
__device__ float g_sum[(size_t)NNODE * H];
__device__ float g_cnt[NNODE];

// ---------- PTX helpers ----------
__device__ __forceinline__ uint32_t smem_u32(const void* p) {
    return (uint32_t)__cvta_generic_to_shared(p);
}
__device__ __forceinline__ void ldsm_x4(uint32_t a[4], uint32_t addr) {
    asm volatile("ldmatrix.sync.aligned.m8n8.x4.shared.b16 {%0,%1,%2,%3}, [%4];"
                 : "=r"(a[0]), "=r"(a[1]), "=r"(a[2]), "=r"(a[3]) : "r"(addr));
}
__device__ __forceinline__ void ldsm_x2_t(uint32_t b[2], uint32_t addr) {
    asm volatile("ldmatrix.sync.aligned.m8n8.x2.trans.shared.b16 {%0,%1}, [%2];"
                 : "=r"(b[0]), "=r"(b[1]) : "r"(addr));
}
__device__ __forceinline__ void mma16816(float c[4], const uint32_t a[4], const uint32_t b[2]) {
    asm volatile("mma.sync.aligned.m16n8k16.row.col.f32.bf16.bf16.f32 "
                 "{%0,%1,%2,%3}, {%4,%5,%6,%7}, {%8,%9}, {%0,%1,%2,%3};"
                 : "+f"(c[0]), "+f"(c[1]), "+f"(c[2]), "+f"(c[3])
                 : "r"(a[0]), "r"(a[1]), "r"(a[2]), "r"(a[3]), "r"(b[0]), "r"(b[1]));
}
__device__ __forceinline__ void red_add_v2(float* p, float x, float y) {
    asm volatile("red.global.add.v2.f32 [%0], {%1, %2};" :: "l"(p), "f"(x), "f"(y) : "memory");
}

// Split a float4 into hi/lo bf16 pairs and store at tile offset (even col).
__device__ __forceinline__ void split_store(__nv_bfloat16* hi, __nv_bfloat16* lo,
                                            int off, float4 v) {
    __nv_bfloat16 h0 = __float2bfloat16(v.x), h1 = __float2bfloat16(v.y);
    __nv_bfloat16 h2 = __float2bfloat16(v.z), h3 = __float2bfloat16(v.w);
    __nv_bfloat16 l0 = __float2bfloat16(v.x - __bfloat162float(h0));
    __nv_bfloat16 l1 = __float2bfloat16(v.y - __bfloat162float(h1));
    __nv_bfloat16 l2 = __float2bfloat16(v.z - __bfloat162float(h2));
    __nv_bfloat16 l3 = __float2bfloat16(v.w - __bfloat162float(h3));
    *(__nv_bfloat162*)(hi + off)     = __nv_bfloat162{h0, h1};
    *(__nv_bfloat162*)(hi + off + 2) = __nv_bfloat162{h2, h3};
    *(__nv_bfloat162*)(lo + off)     = __nv_bfloat162{l0, l1};
    *(__nv_bfloat162*)(lo + off + 2) = __nv_bfloat162{l2, l3};
}

// [BT x 128] @ [128 x 128] in bf16 3-split. Each warp owns 16 rows x 128 cols.
// acc layout (per mma standard): acc[nt][0..1] -> row lane>>2, cols nt*8+(lane&3)*2+{0,1};
//                                acc[nt][2..3] -> row (lane>>2)+8, same cols.
__device__ __forceinline__ void mma_core(const __nv_bfloat16* sXhi, const __nv_bfloat16* sXlo,
                                         const __nv_bfloat16* sWhi, const __nv_bfloat16* sWlo,
                                         int lane, int warp, float acc[16][4]) {
    uint32_t xhi = smem_u32(sXhi), xlo = smem_u32(sXlo);
    uint32_t whi = smem_u32(sWhi), wlo = smem_u32(sWlo);
    int rowA = warp * 16 + (lane & 15);
    uint32_t aoff = (uint32_t)(rowA * STRIDE + ((lane >> 4) << 3)) * 2;
    uint32_t boff = (uint32_t)((lane & 15) * STRIDE) * 2;
#pragma unroll
    for (int k0 = 0; k0 < H; k0 += 16) {
        uint32_t ah[4], al[4];
        ldsm_x4(ah, xhi + aoff + k0 * 2);
        ldsm_x4(al, xlo + aoff + k0 * 2);
#pragma unroll
        for (int nt = 0; nt < 16; nt++) {
            uint32_t bh[2], bl[2];
            uint32_t bo = boff + (uint32_t)(k0 * STRIDE + nt * 8) * 2;
            ldsm_x2_t(bh, whi + bo);
            ldsm_x2_t(bl, wlo + bo);
            mma16816(acc[nt], ah, bh);
            mma16816(acc[nt], ah, bl);
            mma16816(acc[nt], al, bh);
        }
    }
}

// ---- Node precompute: zero g_sum/g_cnt slice; A=nf@We1+be, C=nf@We3, An=nf@Wn1+bn ----
__global__ __launch_bounds__(NT)
void k_node_pre(const float* __restrict__ nf,
                const float* __restrict__ We, const float* __restrict__ be,
                const float* __restrict__ Wn, const float* __restrict__ bn) {
    extern __shared__ __nv_bfloat16 sm[];
    __nv_bfloat16* sXhi = sm;
    __nv_bfloat16* sXlo = sm + TILE;
    __nv_bfloat16* sWhi = sm + 2 * TILE;
    __nv_bfloat16* sWlo = sm + 3 * TILE;
    int t = threadIdx.x, lane = t & 31, warp = t >> 5;
    int nb = blockIdx.x * BT;

    // zero this block's slice of g_sum / g_cnt (replaces a separate kernel)
    for (int idx = t; idx < BT * H4; idx += NT) {
        int n = nb + (idx >> 5);
        if (n < NNODE) ((float4*)g_sum)[(size_t)n * H4 + (idx & 31)] = make_float4(0.f, 0.f, 0.f, 0.f);
    }
    if (t < BT && nb + t < NNODE) g_cnt[nb + t] = 0.f;

    for (int idx = t; idx < BT * H4; idx += NT) {
        int n = nb + (idx >> 5);
        float4 v = make_float4(0.f, 0.f, 0.f, 0.f);
        if (n < NNODE) v = ((const float4*)nf)[(size_t)n * H4 + (idx & 31)];
        split_store(sXhi, sXlo, (idx >> 5) * STRIDE + (idx & 31) * 4, v);
    }

    const float* Ws[3] = { We, We + 2 * H * H, Wn };
    float*       Od[3] = { g_A, g_C, g_An };
    const float* bs[3] = { be, (const float*)0, bn };

    int rq = lane >> 2, cb = (lane & 3) * 2;
    int lr0 = warp * 16 + rq, lr1 = lr0 + 8;

    for (int ph = 0; ph < 3; ph++) {
        __syncthreads();   // all warps done with previous phase's W
        for (int idx = t; idx < H * H4; idx += NT) {
            float4 v = ((const float4*)Ws[ph])[idx];
            split_store(sWhi, sWlo, (idx >> 5) * STRIDE + (idx & 31) * 4, v);
        }
        __syncthreads();

        float acc[16][4];
#pragma unroll
        for (int i = 0; i < 16; i++) { acc[i][0] = acc[i][1] = acc[i][2] = acc[i][3] = 0.f; }
        mma_core(sXhi, sXlo, sWhi, sWlo, lane, warp, acc);

        float* O = Od[ph];
        bool w0 = (nb + lr0) < NNODE, w1 = (nb + lr1) < NNODE;
#pragma unroll
        for (int nt = 0; nt < 16; nt++) {
            int col = nt * 8 + cb;
            float2 b = make_float2(0.f, 0.f);
            if (bs[ph]) b = *(const float2*)&bs[ph][col];
            if (w0) *(float2*)&O[(size_t)(nb + lr0) * H + col] =
                        make_float2(acc[nt][0] + b.x, acc[nt][1] + b.y);
            if (w1) *(float2*)&O[(size_t)(nb + lr1) * H + col] =
                        make_float2(acc[nt][2] + b.x, acc[nt][3] + b.y);
        }
    }
}

// ---- Edge kernel: m = ReLU(A[src] + ef@We2 + C[dst]); out2 = m + ef; scatter mean ----
__global__ __launch_bounds__(NT)
void k_edge(const float* __restrict__ ef,
            const int* __restrict__ src, const int* __restrict__ dst,
            const float* __restrict__ We, float* __restrict__ out2) {
    extern __shared__ __nv_bfloat16 sm[];
    __nv_bfloat16* sXhi = sm;
    __nv_bfloat16* sXlo = sm + TILE;
    __nv_bfloat16* sWhi = sm + 2 * TILE;
    __nv_bfloat16* sWlo = sm + 3 * TILE;
    int* s_src = (int*)(sm + 4 * TILE);
    int* s_dst = s_src + BT;
    int t = threadIdx.x, lane = t & 31, warp = t >> 5;
    int eb = blockIdx.x * BT;

    if (t < BT) { s_src[t] = src[eb + t]; s_dst[t] = dst[eb + t]; }
    const float4* ef4 = (const float4*)(ef + (size_t)eb * H);
    for (int idx = t; idx < BT * H4; idx += NT)
        split_store(sXhi, sXlo, (idx >> 5) * STRIDE + (idx & 31) * 4, ef4[idx]);
    const float4* W4 = (const float4*)(We + H * H);   // We2 rows 128..255
    for (int idx = t; idx < H * H4; idx += NT)
        split_store(sWhi, sWlo, (idx >> 5) * STRIDE + (idx & 31) * 4, W4[idx]);
    __syncthreads();

    float acc[16][4];
#pragma unroll
    for (int i = 0; i < 16; i++) { acc[i][0] = acc[i][1] = acc[i][2] = acc[i][3] = 0.f; }
    mma_core(sXhi, sXlo, sWhi, sWlo, lane, warp, acc);

    int rq = lane >> 2, cb = (lane & 3) * 2;
    int lr0 = warp * 16 + rq, lr1 = lr0 + 8;
    int s0 = s_src[lr0], d0 = s_dst[lr0];
    int s1 = s_src[lr1], d1 = s_dst[lr1];
    if ((lane & 3) == 0) { atomicAdd(&g_cnt[d0], 1.f); atomicAdd(&g_cnt[d1], 1.f); }

#pragma unroll
    for (int nt = 0; nt < 16; nt++) {
        int col = nt * 8 + cb;
        // row lr0
        {
            float2 av = *(const float2*)&g_A[(size_t)s0 * H + col];
            float2 cv = *(const float2*)&g_C[(size_t)d0 * H + col];
            float m0 = fmaxf(acc[nt][0] + av.x + cv.x, 0.f);
            float m1 = fmaxf(acc[nt][1] + av.y + cv.y, 0.f);
            __nv_bfloat162 eh = *(__nv_bfloat162*)&sXhi[lr0 * STRIDE + col];
            __nv_bfloat162 el = *(__nv_bfloat162*)&sXlo[lr0 * STRIDE + col];
            float e0 = __bfloat162float(eh.x) + __bfloat162float(el.x);
            float e1 = __bfloat162float(eh.y) + __bfloat162float(el.y);
            *(float2*)&out2[(size_t)(eb + lr0) * H + col] = make_float2(m0 + e0, m1 + e1);
            red_add_v2(&g_sum[(size_t)d0 * H + col], m0, m1);
        }
        // row lr1
        {
            float2 av = *(const float2*)&g_A[(size_t)s1 * H + col];
            float2 cv = *(const float2*)&g_C[(size_t)d1 * H + col];
            float m0 = fmaxf(acc[nt][2] + av.x + cv.x, 0.f);
            float m1 = fmaxf(acc[nt][3] + av.y + cv.y, 0.f);
            __nv_bfloat162 eh = *(__nv_bfloat162*)&sXhi[lr1 * STRIDE + col];
            __nv_bfloat162 el = *(__nv_bfloat162*)&sXlo[lr1 * STRIDE + col];
            float e0 = __bfloat162float(eh.x) + __bfloat162float(el.x);
            float e1 = __bfloat162float(eh.y) + __bfloat162float(el.y);
            *(float2*)&out2[(size_t)(eb + lr1) * H + col] = make_float2(m0 + e0, m1 + e1);
            red_add_v2(&g_sum[(size_t)d1 * H + col], m0, m1);
        }
    }
}

// ---- Node update: out1 = ReLU(An + (sum/max(cnt,1))@Wn2) + nf ----
__global__ __launch_bounds__(NT)
void k_node_upd(const float* __restrict__ nf,
                const float* __restrict__ Wn, float* __restrict__ out1) {
    extern __shared__ __nv_bfloat16 sm[];
    __nv_bfloat16* sXhi = sm;
    __nv_bfloat16* sXlo = sm + TILE;
    __nv_bfloat16* sWhi = sm + 2 * TILE;
    __nv_bfloat16* sWlo = sm + 3 * TILE;
    int t = threadIdx.x, lane = t & 31, warp = t >> 5;
    int nb = blockIdx.x * BT;

    for (int idx = t; idx < BT * H4; idx += NT) {
        int n = nb + (idx >> 5);
        float4 v = make_float4(0.f, 0.f, 0.f, 0.f);
        if (n < NNODE) {
            v = ((const float4*)g_sum)[(size_t)n * H4 + (idx & 31)];
            float inv = 1.0f / fmaxf(g_cnt[n], 1.0f);
            v.x *= inv; v.y *= inv; v.z *= inv; v.w *= inv;
        }
        split_store(sXhi, sXlo, (idx >> 5) * STRIDE + (idx & 31) * 4, v);
    }
    const float4* W4 = (const float4*)(Wn + H * H);   // Wn2 rows 128..255
    for (int idx = t; idx < H * H4; idx += NT)
        split_store(sWhi, sWlo, (idx >> 5) * STRIDE + (idx & 31) * 4, W4[idx]);
    __syncthreads();

    float acc[16][4];
#pragma unroll
    for (int i = 0; i < 16; i++) { acc[i][0] = acc[i][1] = acc[i][2] = acc[i][3] = 0.f; }
    mma_core(sXhi, sXlo, sWhi, sWlo, lane, warp, acc);

    int rq = lane >> 2, cb = (lane & 3) * 2;
    int lr0 = warp * 16 + rq, lr1 = lr0 + 8;
    bool w0 = (nb + lr0) < NNODE, w1 = (nb + lr1) < NNODE;
#pragma unroll
    for (int nt = 0; nt < 16; nt++) {
        int col = nt * 8 + cb;
        if (w0) {
            float2 an = *(const float2*)&g_An[(size_t)(nb + lr0) * H + col];
            float2 nv = *(const float2*)&nf[(size_t)(nb + lr0) * H + col];
            *(float2*)&out1[(size_t)(nb + lr0) * H + col] =
                make_float2(fmaxf(acc[nt][0] + an.x, 0.f) + nv.x,
                            fmaxf(acc[nt][1] + an.y, 0.f) + nv.y);
        }
        if (w1) {
            float2 an = *(const float2*)&g_An[(size_t)(nb + lr1) * H + col];
            float2 nv = *(const float2*)&nf[(size_t)(nb + lr1) * H + col];
            *(float2*)&out1[(size_t)(nb + lr1) * H + col] =
                make_float2(fmaxf(acc[nt][2] + an.x, 0.f) + nv.x,
                            fmaxf(acc[nt][3] + an.y, 0.f) + nv.y);
        }
    }
}

extern "C" void kernel_launch(void* const* d_in, const int* in_sizes, int n_in,
                              void* d_out, int out_size) {
    const float* nf  = (const float*)d_in[0];
    const float* ef  = (const float*)d_in[1];
    const int*   src = (const int*)d_in[2];
    const int*   dst = (const int*)d_in[3];
    const float* We  = (const float*)d_in[4];
    const float* be  = (const float*)d_in[5];
    const float* Wn  = (const float*)d_in[6];
    const float* bn  = (const float*)d_in[7];
    float* out1 = (float*)d_out;                    // [N,H]
    float* out2 = out1 + (size_t)NNODE * H;         // [E,H]

    const int smem_gemm = 4 * TILE * (int)sizeof(__nv_bfloat16);          // 139264
    const int smem_edge = smem_gemm + 2 * BT * (int)sizeof(int);
    cudaFuncSetAttribute(k_node_pre, cudaFuncAttributeMaxDynamicSharedMemorySize, smem_gemm);
    cudaFuncSetAttribute(k_edge,     cudaFuncAttributeMaxDynamicSharedMemorySize, smem_edge);
    cudaFuncSetAttribute(k_node_upd, cudaFuncAttributeMaxDynamicSharedMemorySize, smem_gemm);

    k_node_pre<<<(NNODE + BT - 1) / BT, NT, smem_gemm>>>(nf, We, be, Wn, bn);
    k_edge<<<NEDGE / BT, NT, smem_edge>>>(ef, src, dst, We, out2);
    k_node_upd<<<(NNODE + BT - 1) / BT, NT, smem_gemm>>>(nf, Wn, out1);
}

// round 5
// speedup vs baseline: 1.5438x; 1.5438x over previous
#include <cuda_runtime.h>
#include <cuda_bf16.h>
#include <cstdint>

// GCNLayer_EdgeCat on GB300 — mma.sync bf16 3-split, occupancy-fixed.
//   We=[We1;We2;We3], Wn=[Wn1;Wn2]:
//     A=nf@We1+be, C=nf@We3, An=nf@Wn1+bn        (k_node_pre)
//     m=ReLU(A[src]+ef@We2+C[dst]); out2=m+ef    (k_edge, scatter mean)
//     out1=ReLU(An+mean@Wn2)+nf                  (k_node_upd)
//   GEMMs: x=hi+lo bf16 split, A@B ~= AhBh+AhBl+AlBh via mma.m16n8k16.
//   BT=64 row tiles + 102.5KB smem -> 2 CTAs/SM (16 warps) for latency hiding.
//   Weights pre-split to bf16 hi/lo images once (k_prep); per-block W fill is
//   a raw uint4 copy.

#define H        128
#define NNODE    50000
#define NEDGE    800000
#define BT       64           // rows per block tile
#define NT       256          // 8 warps: warp = 16 rows x 64 cols
#define STRIDE   136          // bf16 row stride (272B: 16B-aligned, LDSM conflict-free)
#define TILE_A   (BT * STRIDE)
#define TILE_W   (H * STRIDE)

__device__ float g_A  [(size_t)NNODE * H];
__device__ float g_C  [(size_t)NNODE * H];
__device__ float g_An [(size_t)NNODE * H];
__device__ float g_sum[(size_t)NNODE * H];
__device__ float g_cnt[NNODE];
// 5 weights (We1,We2,We3,Wn1,Wn2): [k][n] row-major bf16, hi image then lo image.
__device__ __nv_bfloat16 g_Wimg[5 * 2 * H * H];

// ---------- PTX helpers ----------
__device__ __forceinline__ uint32_t smem_u32(const void* p) {
    return (uint32_t)__cvta_generic_to_shared(p);
}
__device__ __forceinline__ void ldsm_x4(uint32_t a[4], uint32_t addr) {
    asm volatile("ldmatrix.sync.aligned.m8n8.x4.shared.b16 {%0,%1,%2,%3}, [%4];"
                 : "=r"(a[0]), "=r"(a[1]), "=r"(a[2]), "=r"(a[3]) : "r"(addr));
}
__device__ __forceinline__ void ldsm_x2_t(uint32_t b[2], uint32_t addr) {
    asm volatile("ldmatrix.sync.aligned.m8n8.x2.trans.shared.b16 {%0,%1}, [%2];"
                 : "=r"(b[0]), "=r"(b[1]) : "r"(addr));
}
__device__ __forceinline__ void mma16816(float c[4], const uint32_t a[4], const uint32_t b[2]) {
    asm volatile("mma.sync.aligned.m16n8k16.row.col.f32.bf16.bf16.f32 "
                 "{%0,%1,%2,%3}, {%4,%5,%6,%7}, {%8,%9}, {%0,%1,%2,%3};"
                 : "+f"(c[0]), "+f"(c[1]), "+f"(c[2]), "+f"(c[3])
                 : "r"(a[0]), "r"(a[1]), "r"(a[2]), "r"(a[3]), "r"(b[0]), "r"(b[1]));
}
__device__ __forceinline__ void red_add_v2(float* p, float x, float y) {
    asm volatile("red.global.add.v2.f32 [%0], {%1, %2};" :: "l"(p), "f"(x), "f"(y) : "memory");
}

// Split a float4 into hi/lo bf16 pairs and store at element offset off (even).
__device__ __forceinline__ void split_store(__nv_bfloat16* hi, __nv_bfloat16* lo,
                                            int off, float4 v) {
    __nv_bfloat16 h0 = __float2bfloat16(v.x), h1 = __float2bfloat16(v.y);
    __nv_bfloat16 h2 = __float2bfloat16(v.z), h3 = __float2bfloat16(v.w);
    __nv_bfloat16 l0 = __float2bfloat16(v.x - __bfloat162float(h0));
    __nv_bfloat16 l1 = __float2bfloat16(v.y - __bfloat162float(h1));
    __nv_bfloat16 l2 = __float2bfloat16(v.z - __bfloat162float(h2));
    __nv_bfloat16 l3 = __float2bfloat16(v.w - __bfloat162float(h3));
    *(__nv_bfloat162*)(hi + off)     = __nv_bfloat162{h0, h1};
    *(__nv_bfloat162*)(hi + off + 2) = __nv_bfloat162{h2, h3};
    *(__nv_bfloat162*)(lo + off)     = __nv_bfloat162{l0, l1};
    *(__nv_bfloat162*)(lo + off + 2) = __nv_bfloat162{l2, l3};
}

// [BT x 128] @ [128 x 128] -> warp tile 16 rows x 64 cols.
// warp&3 -> row group (16 rows), warp>>2 -> col half (64 cols).
// acc[nt][0..1]: row lane>>2,   cols c0+nt*8+(lane&3)*2+{0,1}
// acc[nt][2..3]: row lane>>2+8, same cols.
__device__ __forceinline__ void mma_core(const __nv_bfloat16* sXhi, const __nv_bfloat16* sXlo,
                                         const __nv_bfloat16* sWhi, const __nv_bfloat16* sWlo,
                                         int lane, int warp, float acc[8][4]) {
    uint32_t xhi = smem_u32(sXhi), xlo = smem_u32(sXlo);
    uint32_t whi = smem_u32(sWhi), wlo = smem_u32(sWlo);
    int r0 = (warp & 3) * 16, c0 = (warp >> 2) * 64;
    uint32_t aoff = (uint32_t)((r0 + (lane & 15)) * STRIDE + ((lane >> 4) << 3)) * 2;
    uint32_t boff = (uint32_t)((lane & 15) * STRIDE + c0) * 2;
#pragma unroll
    for (int k0 = 0; k0 < H; k0 += 16) {
        uint32_t ah[4], al[4];
        ldsm_x4(ah, xhi + aoff + k0 * (STRIDE * 0 + 2));   // +k0 elems along row
        ldsm_x4(al, xlo + aoff + k0 * 2);
#pragma unroll
        for (int nt = 0; nt < 8; nt++) {
            uint32_t bh[2], bl[2];
            uint32_t bo = boff + (uint32_t)(k0 * STRIDE + nt * 8) * 2;
            ldsm_x2_t(bh, whi + bo);
            ldsm_x2_t(bl, wlo + bo);
            mma16816(acc[nt], ah, bh);
            mma16816(acc[nt], ah, bl);
            mma16816(acc[nt], al, bh);
        }
    }
}

// Copy a prepped W image pair (hi+lo, [k][n] 128x128 bf16) into padded smem.
__device__ __forceinline__ void fill_W(__nv_bfloat16* sWhi, __nv_bfloat16* sWlo,
                                       int wsel, int t) {
    const uint4* hi4 = (const uint4*)(g_Wimg + (size_t)wsel * 2 * H * H);
    const uint4* lo4 = hi4 + (H * H / 8);
    for (int i = t; i < H * H / 8; i += NT) {         // 2048 uint4 per image
        int row = i >> 4, c8 = (i & 15) * 8;
        *(uint4*)(sWhi + row * STRIDE + c8) = hi4[i];
        *(uint4*)(sWlo + row * STRIDE + c8) = lo4[i];
    }
}

// ---- k_prep: split weights into bf16 hi/lo [k][n] images (once) ----
__global__ void k_prep(const float* __restrict__ We, const float* __restrict__ Wn) {
    int idx = blockIdx.x * blockDim.x + threadIdx.x;
    if (idx >= 5 * H * H) return;
    int w = idx / (H * H), r = idx % (H * H);
    const float* src = (w < 3) ? (We + w * H * H) : (Wn + (w - 3) * H * H);
    float v = src[r];
    __nv_bfloat16 hi = __float2bfloat16(v);
    __nv_bfloat16 lo = __float2bfloat16(v - __bfloat162float(hi));
    g_Wimg[(size_t)w * 2 * H * H + r] = hi;
    g_Wimg[(size_t)w * 2 * H * H + H * H + r] = lo;
}

// ---- k_node_pre: zero sums; A=nf@We1+be, C=nf@We3, An=nf@Wn1+bn ----
__global__ __launch_bounds__(NT, 2)
void k_node_pre(const float* __restrict__ nf,
                const float* __restrict__ be, const float* __restrict__ bn) {
    extern __shared__ __align__(16) __nv_bfloat16 sm[];
    __nv_bfloat16* sXhi = sm;
    __nv_bfloat16* sXlo = sm + TILE_A;
    __nv_bfloat16* sWhi = sm + 2 * TILE_A;
    __nv_bfloat16* sWlo = sm + 2 * TILE_A + TILE_W;
    int t = threadIdx.x, lane = t & 31, warp = t >> 5;
    int nb = blockIdx.x * BT;

    // zero g_sum / g_cnt slice
    for (int i = t; i < BT * 32; i += NT) {
        int n = nb + (i >> 5);
        if (n < NNODE) ((float4*)g_sum)[(size_t)n * 32 + (i & 31)] = make_float4(0.f, 0.f, 0.f, 0.f);
    }
    if (t < BT && nb + t < NNODE) g_cnt[nb + t] = 0.f;

    for (int i = t; i < BT * 32; i += NT) {
        int n = nb + (i >> 5);
        float4 v = make_float4(0.f, 0.f, 0.f, 0.f);
        if (n < NNODE) v = ((const float4*)nf)[(size_t)n * 32 + (i & 31)];
        split_store(sXhi, sXlo, (i >> 5) * STRIDE + (i & 31) * 4, v);
    }

    const int    wsel[3] = {0, 2, 3};
    float*       Od[3]   = {g_A, g_C, g_An};
    const float* bias[3] = {be, (const float*)0, bn};

    int rq = (lane >> 2), cb = (warp >> 2) * 64 + (lane & 3) * 2;
    int lr0 = (warp & 3) * 16 + rq, lr1 = lr0 + 8;

    for (int ph = 0; ph < 3; ph++) {
        __syncthreads();                 // previous phase's W fully consumed
        fill_W(sWhi, sWlo, wsel[ph], t);
        __syncthreads();

        float acc[8][4];
#pragma unroll
        for (int i = 0; i < 8; i++) acc[i][0] = acc[i][1] = acc[i][2] = acc[i][3] = 0.f;
        mma_core(sXhi, sXlo, sWhi, sWlo, lane, warp, acc);

        float* O = Od[ph];
        bool w0 = (nb + lr0) < NNODE, w1 = (nb + lr1) < NNODE;
#pragma unroll
        for (int nt = 0; nt < 8; nt++) {
            int col = cb + nt * 8;
            float2 b = make_float2(0.f, 0.f);
            if (bias[ph]) b = *(const float2*)&bias[ph][col];
            if (w0) *(float2*)&O[(size_t)(nb + lr0) * H + col] =
                        make_float2(acc[nt][0] + b.x, acc[nt][1] + b.y);
            if (w1) *(float2*)&O[(size_t)(nb + lr1) * H + col] =
                        make_float2(acc[nt][2] + b.x, acc[nt][3] + b.y);
        }
    }
}

// ---- k_edge: m = ReLU(A[src] + ef@We2 + C[dst]); out2 = m+ef; scatter mean ----
__global__ __launch_bounds__(NT, 2)
void k_edge(const float* __restrict__ ef,
            const int* __restrict__ src, const int* __restrict__ dst,
            float* __restrict__ out2) {
    extern __shared__ __align__(16) __nv_bfloat16 sm[];
    __nv_bfloat16* sXhi = sm;
    __nv_bfloat16* sXlo = sm + TILE_A;
    __nv_bfloat16* sWhi = sm + 2 * TILE_A;
    __nv_bfloat16* sWlo = sm + 2 * TILE_A + TILE_W;
    int* s_src = (int*)(sm + 2 * TILE_A + 2 * TILE_W);
    int* s_dst = s_src + BT;
    int t = threadIdx.x, lane = t & 31, warp = t >> 5;
    int eb = blockIdx.x * BT;

    if (t < BT) { s_src[t] = src[eb + t]; s_dst[t] = dst[eb + t]; }
    const float4* ef4 = (const float4*)(ef + (size_t)eb * H);
    for (int i = t; i < BT * 32; i += NT)
        split_store(sXhi, sXlo, (i >> 5) * STRIDE + (i & 31) * 4, ef4[i]);
    fill_W(sWhi, sWlo, 1, t);                        // We2
    __syncthreads();

    float acc[8][4];
#pragma unroll
    for (int i = 0; i < 8; i++) acc[i][0] = acc[i][1] = acc[i][2] = acc[i][3] = 0.f;
    mma_core(sXhi, sXlo, sWhi, sWlo, lane, warp, acc);

    int rq = lane >> 2, cb = (warp >> 2) * 64 + (lane & 3) * 2;
    int lr0 = (warp & 3) * 16 + rq, lr1 = lr0 + 8;
    int s0 = s_src[lr0], d0 = s_dst[lr0];
    int s1 = s_src[lr1], d1 = s_dst[lr1];
    if ((warp >> 2) == 0 && (lane & 3) == 0) {
        atomicAdd(&g_cnt[d0], 1.f); atomicAdd(&g_cnt[d1], 1.f);
    }

#pragma unroll
    for (int nt = 0; nt < 8; nt++) {
        int col = cb + nt * 8;
        {   // row lr0
            float2 av = *(const float2*)&g_A[(size_t)s0 * H + col];
            float2 cv = *(const float2*)&g_C[(size_t)d0 * H + col];
            float m0 = fmaxf(acc[nt][0] + av.x + cv.x, 0.f);
            float m1 = fmaxf(acc[nt][1] + av.y + cv.y, 0.f);
            __nv_bfloat162 eh = *(__nv_bfloat162*)&sXhi[lr0 * STRIDE + col];
            __nv_bfloat162 el = *(__nv_bfloat162*)&sXlo[lr0 * STRIDE + col];
            *(float2*)&out2[(size_t)(eb + lr0) * H + col] =
                make_float2(m0 + __bfloat162float(eh.x) + __bfloat162float(el.x),
                            m1 + __bfloat162float(eh.y) + __bfloat162float(el.y));
            red_add_v2(&g_sum[(size_t)d0 * H + col], m0, m1);
        }
        {   // row lr1
            float2 av = *(const float2*)&g_A[(size_t)s1 * H + col];
            float2 cv = *(const float2*)&g_C[(size_t)d1 * H + col];
            float m0 = fmaxf(acc[nt][2] + av.x + cv.x, 0.f);
            float m1 = fmaxf(acc[nt][3] + av.y + cv.y, 0.f);
            __nv_bfloat162 eh = *(__nv_bfloat162*)&sXhi[lr1 * STRIDE + col];
            __nv_bfloat162 el = *(__nv_bfloat162*)&sXlo[lr1 * STRIDE + col];
            *(float2*)&out2[(size_t)(eb + lr1) * H + col] =
                make_float2(m0 + __bfloat162float(eh.x) + __bfloat162float(el.x),
                            m1 + __bfloat162float(eh.y) + __bfloat162float(el.y));
            red_add_v2(&g_sum[(size_t)d1 * H + col], m0, m1);
        }
    }
}

// ---- k_node_upd: out1 = ReLU(An + (sum/max(cnt,1))@Wn2) + nf ----
__global__ __launch_bounds__(NT, 2)
void k_node_upd(const float* __restrict__ nf, float* __restrict__ out1) {
    extern __shared__ __align__(16) __nv_bfloat16 sm[];
    __nv_bfloat16* sXhi = sm;
    __nv_bfloat16* sXlo = sm + TILE_A;
    __nv_bfloat16* sWhi = sm + 2 * TILE_A;
    __nv_bfloat16* sWlo = sm + 2 * TILE_A + TILE_W;
    int t = threadIdx.x, lane = t & 31, warp = t >> 5;
    int nb = blockIdx.x * BT;

    for (int i = t; i < BT * 32; i += NT) {
        int n = nb + (i >> 5);
        float4 v = make_float4(0.f, 0.f, 0.f, 0.f);
        if (n < NNODE) {
            v = ((const float4*)g_sum)[(size_t)n * 32 + (i & 31)];
            float inv = 1.0f / fmaxf(g_cnt[n], 1.0f);
            v.x *= inv; v.y *= inv; v.z *= inv; v.w *= inv;
        }
        split_store(sXhi, sXlo, (i >> 5) * STRIDE + (i & 31) * 4, v);
    }
    fill_W(sWhi, sWlo, 4, t);                        // Wn2
    __syncthreads();

    float acc[8][4];
#pragma unroll
    for (int i = 0; i < 8; i++) acc[i][0] = acc[i][1] = acc[i][2] = acc[i][3] = 0.f;
    mma_core(sXhi, sXlo, sWhi, sWlo, lane, warp, acc);

    int rq = lane >> 2, cb = (warp >> 2) * 64 + (lane & 3) * 2;
    int lr0 = (warp & 3) * 16 + rq, lr1 = lr0 + 8;
    bool w0 = (nb + lr0) < NNODE, w1 = (nb + lr1) < NNODE;
#pragma unroll
    for (int nt = 0; nt < 8; nt++) {
        int col = cb + nt * 8;
        if (w0) {
            float2 an = *(const float2*)&g_An[(size_t)(nb + lr0) * H + col];
            float2 nv = *(const float2*)&nf[(size_t)(nb + lr0) * H + col];
            *(float2*)&out1[(size_t)(nb + lr0) * H + col] =
                make_float2(fmaxf(acc[nt][0] + an.x, 0.f) + nv.x,
                            fmaxf(acc[nt][1] + an.y, 0.f) + nv.y);
        }
        if (w1) {
            float2 an = *(const float2*)&g_An[(size_t)(nb + lr1) * H + col];
            float2 nv = *(const float2*)&nf[(size_t)(nb + lr1) * H + col];
            *(float2*)&out1[(size_t)(nb + lr1) * H + col] =
                make_float2(fmaxf(acc[nt][2] + an.x, 0.f) + nv.x,
                            fmaxf(acc[nt][3] + an.y, 0.f) + nv.y);
        }
    }
}

extern "C" void kernel_launch(void* const* d_in, const int* in_sizes, int n_in,
                              void* d_out, int out_size) {
    const float* nf  = (const float*)d_in[0];
    const float* ef  = (const float*)d_in[1];
    const int*   src = (const int*)d_in[2];
    const int*   dst = (const int*)d_in[3];
    const float* We  = (const float*)d_in[4];
    const float* be  = (const float*)d_in[5];
    const float* Wn  = (const float*)d_in[6];
    const float* bn  = (const float*)d_in[7];
    float* out1 = (float*)d_out;                    // [N,H]
    float* out2 = out1 + (size_t)NNODE * H;         // [E,H]

    const int smem_gemm = (2 * TILE_A + 2 * TILE_W) * (int)sizeof(__nv_bfloat16); // 104448
    const int smem_edge = smem_gemm + 2 * BT * (int)sizeof(int);                  // +512
    cudaFuncSetAttribute(k_node_pre, cudaFuncAttributeMaxDynamicSharedMemorySize, smem_gemm);
    cudaFuncSetAttribute(k_edge,     cudaFuncAttributeMaxDynamicSharedMemorySize, smem_edge);
    cudaFuncSetAttribute(k_node_upd, cudaFuncAttributeMaxDynamicSharedMemorySize, smem_gemm);

    k_prep<<<(5 * H * H + 255) / 256, 256>>>(We, Wn);
    k_node_pre<<<(NNODE + BT - 1) / BT, NT, smem_gemm>>>(nf, be, bn);
    k_edge<<<NEDGE / BT, NT, smem_edge>>>(ef, src, dst, out2);
    k_node_upd<<<(NNODE + BT - 1) / BT, NT, smem_gemm>>>(nf, out1);
}

// round 6
// speedup vs baseline: 1.8626x; 1.2065x over previous
#include <cuda_runtime.h>
#include <cuda_bf16.h>
#include <cstdint>

// GCNLayer_EdgeCat on GB300 — mma.sync bf16 3-split, R6:
//   * ldmatrix.x4.trans for B (halves B LDSM count)
//   * 4 edge tiles per block (amortizes We2 smem refill: 800MB -> 200MB L2)
//   We=[We1;We2;We3], Wn=[Wn1;Wn2]:
//     A=nf@We1+be, C=nf@We3, An=nf@Wn1+bn        (k_node_pre)
//     m=ReLU(A[src]+ef@We2+C[dst]); out2=m+ef    (k_edge, scatter mean)
//     out1=ReLU(An+mean@Wn2)+nf                  (k_node_upd)

#define H        128
#define NNODE    50000
#define NEDGE    800000
#define BT       64           // rows per tile
#define NT       256          // 8 warps: warp = 16 rows x 64 cols
#define TPB      4            // edge tiles per block
#define STRIDE   136          // bf16 row stride (272B, LDSM conflict-free)
#define TILE_A   (BT * STRIDE)
#define TILE_W   (H * STRIDE)

__device__ float g_A  [(size_t)NNODE * H];
__device__ float g_C  [(size_t)NNODE * H];
__device__ float g_An [(size_t)NNODE * H];
__device__ float g_sum[(size_t)NNODE * H];
__device__ float g_cnt[NNODE];
// 5 weights (We1,We2,We3,Wn1,Wn2): [k][n] row-major bf16, hi image then lo image.
__device__ __nv_bfloat16 g_Wimg[5 * 2 * H * H];

// ---------- PTX helpers ----------
__device__ __forceinline__ uint32_t smem_u32(const void* p) {
    return (uint32_t)__cvta_generic_to_shared(p);
}
__device__ __forceinline__ void ldsm_x4(uint32_t a[4], uint32_t addr) {
    asm volatile("ldmatrix.sync.aligned.m8n8.x4.shared.b16 {%0,%1,%2,%3}, [%4];"
                 : "=r"(a[0]), "=r"(a[1]), "=r"(a[2]), "=r"(a[3]) : "r"(addr));
}
__device__ __forceinline__ void ldsm_x4_t(uint32_t b[4], uint32_t addr) {
    asm volatile("ldmatrix.sync.aligned.m8n8.x4.trans.shared.b16 {%0,%1,%2,%3}, [%4];"
                 : "=r"(b[0]), "=r"(b[1]), "=r"(b[2]), "=r"(b[3]) : "r"(addr));
}
__device__ __forceinline__ void mma16816(float c[4], const uint32_t a[4], const uint32_t b[2]) {
    asm volatile("mma.sync.aligned.m16n8k16.row.col.f32.bf16.bf16.f32 "
                 "{%0,%1,%2,%3}, {%4,%5,%6,%7}, {%8,%9}, {%0,%1,%2,%3};"
                 : "+f"(c[0]), "+f"(c[1]), "+f"(c[2]), "+f"(c[3])
                 : "r"(a[0]), "r"(a[1]), "r"(a[2]), "r"(a[3]), "r"(b[0]), "r"(b[1]));
}
__device__ __forceinline__ void red_add_v2(float* p, float x, float y) {
    asm volatile("red.global.add.v2.f32 [%0], {%1, %2};" :: "l"(p), "f"(x), "f"(y) : "memory");
}

// Split a float4 into hi/lo bf16 pairs and store at element offset off (even).
__device__ __forceinline__ void split_store(__nv_bfloat16* hi, __nv_bfloat16* lo,
                                            int off, float4 v) {
    __nv_bfloat16 h0 = __float2bfloat16(v.x), h1 = __float2bfloat16(v.y);
    __nv_bfloat16 h2 = __float2bfloat16(v.z), h3 = __float2bfloat16(v.w);
    __nv_bfloat16 l0 = __float2bfloat16(v.x - __bfloat162float(h0));
    __nv_bfloat16 l1 = __float2bfloat16(v.y - __bfloat162float(h1));
    __nv_bfloat16 l2 = __float2bfloat16(v.z - __bfloat162float(h2));
    __nv_bfloat16 l3 = __float2bfloat16(v.w - __bfloat162float(h3));
    *(__nv_bfloat162*)(hi + off)     = __nv_bfloat162{h0, h1};
    *(__nv_bfloat162*)(hi + off + 2) = __nv_bfloat162{h2, h3};
    *(__nv_bfloat162*)(lo + off)     = __nv_bfloat162{l0, l1};
    *(__nv_bfloat162*)(lo + off + 2) = __nv_bfloat162{l2, l3};
}

// [BT x 128] @ [128 x 128] -> warp tile 16 rows x 64 cols.
// warp&3 -> row group, warp>>2 -> col half.
// acc[nt][0..1]: row lane>>2,   cols c0+nt*8+(lane&3)*2+{0,1}
// acc[nt][2..3]: row lane>>2+8, same cols.
// B loaded with x4.trans: one LDSM covers two adjacent n-tiles.
__device__ __forceinline__ void mma_core(const __nv_bfloat16* sXhi, const __nv_bfloat16* sXlo,
                                         const __nv_bfloat16* sWhi, const __nv_bfloat16* sWlo,
                                         int lane, int warp, float acc[8][4]) {
    uint32_t xhi = smem_u32(sXhi), xlo = smem_u32(sXlo);
    uint32_t whi = smem_u32(sWhi), wlo = smem_u32(sWlo);
    int r0 = (warp & 3) * 16, c0 = (warp >> 2) * 64;
    uint32_t aoff = (uint32_t)((r0 + (lane & 15)) * STRIDE + ((lane >> 4) << 3)) * 2;
    // B: lanes 0-15 -> k rows (n-tile ntp*2), lanes 16-31 -> same k rows, +8 cols
    uint32_t boff = (uint32_t)((lane & 15) * STRIDE + c0 + ((lane >> 4) << 3)) * 2;
#pragma unroll
    for (int k0 = 0; k0 < H; k0 += 16) {
        uint32_t ah[4], al[4];
        ldsm_x4(ah, xhi + aoff + k0 * 2);
        ldsm_x4(al, xlo + aoff + k0 * 2);
#pragma unroll
        for (int ntp = 0; ntp < 4; ntp++) {
            uint32_t bh[4], bl[4];
            uint32_t bo = boff + (uint32_t)(k0 * STRIDE + ntp * 16) * 2;
            ldsm_x4_t(bh, whi + bo);
            ldsm_x4_t(bl, wlo + bo);
            // two interleaved accumulator chains for ILP
            mma16816(acc[2 * ntp],     ah, bh + 0);
            mma16816(acc[2 * ntp + 1], ah, bh + 2);
            mma16816(acc[2 * ntp],     ah, bl + 0);
            mma16816(acc[2 * ntp + 1], ah, bl + 2);
            mma16816(acc[2 * ntp],     al, bh + 0);
            mma16816(acc[2 * ntp + 1], al, bh + 2);
        }
    }
}

// Copy a prepped W image pair (hi+lo, [k][n] 128x128 bf16) into padded smem.
__device__ __forceinline__ void fill_W(__nv_bfloat16* sWhi, __nv_bfloat16* sWlo,
                                       int wsel, int t) {
    const uint4* hi4 = (const uint4*)(g_Wimg + (size_t)wsel * 2 * H * H);
    const uint4* lo4 = hi4 + (H * H / 8);
    for (int i = t; i < H * H / 8; i += NT) {         // 2048 uint4 per image
        int row = i >> 4, c8 = (i & 15) * 8;
        *(uint4*)(sWhi + row * STRIDE + c8) = hi4[i];
        *(uint4*)(sWlo + row * STRIDE + c8) = lo4[i];
    }
}

// ---- k_prep: split weights into bf16 hi/lo [k][n] images (once) ----
__global__ void k_prep(const float* __restrict__ We, const float* __restrict__ Wn) {
    int idx = blockIdx.x * blockDim.x + threadIdx.x;
    if (idx >= 5 * H * H) return;
    int w = idx / (H * H), r = idx % (H * H);
    const float* src = (w < 3) ? (We + w * H * H) : (Wn + (w - 3) * H * H);
    float v = src[r];
    __nv_bfloat16 hi = __float2bfloat16(v);
    __nv_bfloat16 lo = __float2bfloat16(v - __bfloat162float(hi));
    g_Wimg[(size_t)w * 2 * H * H + r] = hi;
    g_Wimg[(size_t)w * 2 * H * H + H * H + r] = lo;
}

// ---- k_node_pre: zero sums; A=nf@We1+be, C=nf@We3, An=nf@Wn1+bn ----
__global__ __launch_bounds__(NT, 2)
void k_node_pre(const float* __restrict__ nf,
                const float* __restrict__ be, const float* __restrict__ bn) {
    extern __shared__ __align__(16) __nv_bfloat16 sm[];
    __nv_bfloat16* sXhi = sm;
    __nv_bfloat16* sXlo = sm + TILE_A;
    __nv_bfloat16* sWhi = sm + 2 * TILE_A;
    __nv_bfloat16* sWlo = sm + 2 * TILE_A + TILE_W;
    int t = threadIdx.x, lane = t & 31, warp = t >> 5;
    int nb = blockIdx.x * BT;

    // zero g_sum / g_cnt slice
    for (int i = t; i < BT * 32; i += NT) {
        int n = nb + (i >> 5);
        if (n < NNODE) ((float4*)g_sum)[(size_t)n * 32 + (i & 31)] = make_float4(0.f, 0.f, 0.f, 0.f);
    }
    if (t < BT && nb + t < NNODE) g_cnt[nb + t] = 0.f;

    for (int i = t; i < BT * 32; i += NT) {
        int n = nb + (i >> 5);
        float4 v = make_float4(0.f, 0.f, 0.f, 0.f);
        if (n < NNODE) v = ((const float4*)nf)[(size_t)n * 32 + (i & 31)];
        split_store(sXhi, sXlo, (i >> 5) * STRIDE + (i & 31) * 4, v);
    }

    const int    wsel[3] = {0, 2, 3};
    float*       Od[3]   = {g_A, g_C, g_An};
    const float* bias[3] = {be, (const float*)0, bn};

    int rq = (lane >> 2), cb = (warp >> 2) * 64 + (lane & 3) * 2;
    int lr0 = (warp & 3) * 16 + rq, lr1 = lr0 + 8;

    for (int ph = 0; ph < 3; ph++) {
        __syncthreads();                 // previous phase's W fully consumed
        fill_W(sWhi, sWlo, wsel[ph], t);
        __syncthreads();

        float acc[8][4];
#pragma unroll
        for (int i = 0; i < 8; i++) acc[i][0] = acc[i][1] = acc[i][2] = acc[i][3] = 0.f;
        mma_core(sXhi, sXlo, sWhi, sWlo, lane, warp, acc);

        float* O = Od[ph];
        bool w0 = (nb + lr0) < NNODE, w1 = (nb + lr1) < NNODE;
#pragma unroll
        for (int nt = 0; nt < 8; nt++) {
            int col = cb + nt * 8;
            float2 b = make_float2(0.f, 0.f);
            if (bias[ph]) b = *(const float2*)&bias[ph][col];
            if (w0) *(float2*)&O[(size_t)(nb + lr0) * H + col] =
                        make_float2(acc[nt][0] + b.x, acc[nt][1] + b.y);
            if (w1) *(float2*)&O[(size_t)(nb + lr1) * H + col] =
                        make_float2(acc[nt][2] + b.x, acc[nt][3] + b.y);
        }
    }
}

// ---- k_edge: 4 tiles/block. m = ReLU(A[src]+ef@We2+C[dst]); out2=m+ef; scatter mean ----
__global__ __launch_bounds__(NT, 2)
void k_edge(const float* __restrict__ ef,
            const int* __restrict__ src, const int* __restrict__ dst,
            float* __restrict__ out2) {
    extern __shared__ __align__(16) __nv_bfloat16 sm[];
    __nv_bfloat16* sXhi = sm;
    __nv_bfloat16* sXlo = sm + TILE_A;
    __nv_bfloat16* sWhi = sm + 2 * TILE_A;
    __nv_bfloat16* sWlo = sm + 2 * TILE_A + TILE_W;
    int* s_src = (int*)(sm + 2 * TILE_A + 2 * TILE_W);
    int* s_dst = s_src + BT;
    int t = threadIdx.x, lane = t & 31, warp = t >> 5;

    fill_W(sWhi, sWlo, 1, t);                        // We2, resident for all tiles

    int rq = lane >> 2, cb = (warp >> 2) * 64 + (lane & 3) * 2;
    int lr0 = (warp & 3) * 16 + rq, lr1 = lr0 + 8;

    for (int tt = 0; tt < TPB; tt++) {
        int eb = (blockIdx.x * TPB + tt) * BT;
        if (tt) __syncthreads();                     // epilogue(t-1) done with sX
        if (t < BT) { s_src[t] = src[eb + t]; s_dst[t] = dst[eb + t]; }
        const float4* ef4 = (const float4*)(ef + (size_t)eb * H);
        for (int i = t; i < BT * 32; i += NT)
            split_store(sXhi, sXlo, (i >> 5) * STRIDE + (i & 31) * 4, ef4[i]);
        __syncthreads();

        float acc[8][4];
#pragma unroll
        for (int i = 0; i < 8; i++) acc[i][0] = acc[i][1] = acc[i][2] = acc[i][3] = 0.f;
        mma_core(sXhi, sXlo, sWhi, sWlo, lane, warp, acc);

        int s0 = s_src[lr0], d0 = s_dst[lr0];
        int s1 = s_src[lr1], d1 = s_dst[lr1];
        if ((warp >> 2) == 0 && (lane & 3) == 0) {
            atomicAdd(&g_cnt[d0], 1.f); atomicAdd(&g_cnt[d1], 1.f);
        }

#pragma unroll
        for (int nt = 0; nt < 8; nt++) {
            int col = cb + nt * 8;
            {   // row lr0
                float2 av = *(const float2*)&g_A[(size_t)s0 * H + col];
                float2 cv = *(const float2*)&g_C[(size_t)d0 * H + col];
                float m0 = fmaxf(acc[nt][0] + av.x + cv.x, 0.f);
                float m1 = fmaxf(acc[nt][1] + av.y + cv.y, 0.f);
                __nv_bfloat162 eh = *(__nv_bfloat162*)&sXhi[lr0 * STRIDE + col];
                __nv_bfloat162 el = *(__nv_bfloat162*)&sXlo[lr0 * STRIDE + col];
                *(float2*)&out2[(size_t)(eb + lr0) * H + col] =
                    make_float2(m0 + __bfloat162float(eh.x) + __bfloat162float(el.x),
                                m1 + __bfloat162float(eh.y) + __bfloat162float(el.y));
                red_add_v2(&g_sum[(size_t)d0 * H + col], m0, m1);
            }
            {   // row lr1
                float2 av = *(const float2*)&g_A[(size_t)s1 * H + col];
                float2 cv = *(const float2*)&g_C[(size_t)d1 * H + col];
                float m0 = fmaxf(acc[nt][2] + av.x + cv.x, 0.f);
                float m1 = fmaxf(acc[nt][3] + av.y + cv.y, 0.f);
                __nv_bfloat162 eh = *(__nv_bfloat162*)&sXhi[lr1 * STRIDE + col];
                __nv_bfloat162 el = *(__nv_bfloat162*)&sXlo[lr1 * STRIDE + col];
                *(float2*)&out2[(size_t)(eb + lr1) * H + col] =
                    make_float2(m0 + __bfloat162float(eh.x) + __bfloat162float(el.x),
                                m1 + __bfloat162float(eh.y) + __bfloat162float(el.y));
                red_add_v2(&g_sum[(size_t)d1 * H + col], m0, m1);
            }
        }
    }
}

// ---- k_node_upd: out1 = ReLU(An + (sum/max(cnt,1))@Wn2) + nf ----
__global__ __launch_bounds__(NT, 2)
void k_node_upd(const float* __restrict__ nf, float* __restrict__ out1) {
    extern __shared__ __align__(16) __nv_bfloat16 sm[];
    __nv_bfloat16* sXhi = sm;
    __nv_bfloat16* sXlo = sm + TILE_A;
    __nv_bfloat16* sWhi = sm + 2 * TILE_A;
    __nv_bfloat16* sWlo = sm + 2 * TILE_A + TILE_W;
    int t = threadIdx.x, lane = t & 31, warp = t >> 5;
    int nb = blockIdx.x * BT;

    for (int i = t; i < BT * 32; i += NT) {
        int n = nb + (i >> 5);
        float4 v = make_float4(0.f, 0.f, 0.f, 0.f);
        if (n < NNODE) {
            v = ((const float4*)g_sum)[(size_t)n * 32 + (i & 31)];
            float inv = 1.0f / fmaxf(g_cnt[n], 1.0f);
            v.x *= inv; v.y *= inv; v.z *= inv; v.w *= inv;
        }
        split_store(sXhi, sXlo, (i >> 5) * STRIDE + (i & 31) * 4, v);
    }
    fill_W(sWhi, sWlo, 4, t);                        // Wn2
    __syncthreads();

    float acc[8][4];
#pragma unroll
    for (int i = 0; i < 8; i++) acc[i][0] = acc[i][1] = acc[i][2] = acc[i][3] = 0.f;
    mma_core(sXhi, sXlo, sWhi, sWlo, lane, warp, acc);

    int rq = lane >> 2, cb = (warp >> 2) * 64 + (lane & 3) * 2;
    int lr0 = (warp & 3) * 16 + rq, lr1 = lr0 + 8;
    bool w0 = (nb + lr0) < NNODE, w1 = (nb + lr1) < NNODE;
#pragma unroll
    for (int nt = 0; nt < 8; nt++) {
        int col = cb + nt * 8;
        if (w0) {
            float2 an = *(const float2*)&g_An[(size_t)(nb + lr0) * H + col];
            float2 nv = *(const float2*)&nf[(size_t)(nb + lr0) * H + col];
            *(float2*)&out1[(size_t)(nb + lr0) * H + col] =
                make_float2(fmaxf(acc[nt][0] + an.x, 0.f) + nv.x,
                            fmaxf(acc[nt][1] + an.y, 0.f) + nv.y);
        }
        if (w1) {
            float2 an = *(const float2*)&g_An[(size_t)(nb + lr1) * H + col];
            float2 nv = *(const float2*)&nf[(size_t)(nb + lr1) * H + col];
            *(float2*)&out1[(size_t)(nb + lr1) * H + col] =
                make_float2(fmaxf(acc[nt][2] + an.x, 0.f) + nv.x,
                            fmaxf(acc[nt][3] + an.y, 0.f) + nv.y);
        }
    }
}

extern "C" void kernel_launch(void* const* d_in, const int* in_sizes, int n_in,
                              void* d_out, int out_size) {
    const float* nf  = (const float*)d_in[0];
    const float* ef  = (const float*)d_in[1];
    const int*   src = (const int*)d_in[2];
    const int*   dst = (const int*)d_in[3];
    const float* We  = (const float*)d_in[4];
    const float* be  = (const float*)d_in[5];
    const float* Wn  = (const float*)d_in[6];
    const float* bn  = (const float*)d_in[7];
    float* out1 = (float*)d_out;                    // [N,H]
    float* out2 = out1 + (size_t)NNODE * H;         // [E,H]

    const int smem_gemm = (2 * TILE_A + 2 * TILE_W) * (int)sizeof(__nv_bfloat16); // 104448
    const int smem_edge = smem_gemm + 2 * BT * (int)sizeof(int);                  // +512
    cudaFuncSetAttribute(k_node_pre, cudaFuncAttributeMaxDynamicSharedMemorySize, smem_gemm);
    cudaFuncSetAttribute(k_edge,     cudaFuncAttributeMaxDynamicSharedMemorySize, smem_edge);
    cudaFuncSetAttribute(k_node_upd, cudaFuncAttributeMaxDynamicSharedMemorySize, smem_gemm);

    k_prep<<<(5 * H * H + 255) / 256, 256>>>(We, Wn);
    k_node_pre<<<(NNODE + BT - 1) / BT, NT, smem_gemm>>>(nf, be, bn);
    k_edge<<<NEDGE / (BT * TPB), NT, smem_edge>>>(ef, src, dst, out2);
    k_node_upd<<<(NNODE + BT - 1) / BT, NT, smem_gemm>>>(nf, out1);
}